// round 16
// baseline (speedup 1.0000x reference)
#include <cuda_runtime.h>
#include <cuda_bf16.h>
#include <cuda_fp8.h>
#include <cstdint>

// Problem constants
#define DIM_X 1024
#define H1    2048
#define H2    512
#define SL    8192
#define SU    16384
#define K_TRIES 8

#define INV64 0.015625f

// ---------------------------------------------------------------------------
// Device scratch (no allocations). 16B-aligned for cp.async.
// Weights pre-scaled x64 (exact). fp8 arrays: e4m3 of value, e5m2 of (v - bf16(v)).
// ---------------------------------------------------------------------------
__device__ __align__(16) __nv_bfloat16 g_Xu_hi[(size_t)SU * DIM_X];
__device__ __align__(16) uint8_t       g_Xu_8 [(size_t)SU * DIM_X];
__device__ __align__(16) uint8_t       g_Xu_8L[(size_t)SU * DIM_X];
__device__ __align__(16) __nv_bfloat16 g_Xl_hi[(size_t)SL * DIM_X];
__device__ __align__(16) uint8_t       g_Xl_8 [(size_t)SL * DIM_X];
__device__ __align__(16) uint8_t       g_Xl_8L[(size_t)SL * DIM_X];
__device__ __align__(16) __nv_bfloat16 g_W1_hi[(size_t)DIM_X * H1];   // [K][N] x64
__device__ __align__(16) uint8_t       g_W1T_8 [(size_t)H1 * DIM_X];  // [N][K] x64
__device__ __align__(16) uint8_t       g_W1T_8L[(size_t)H1 * DIM_X];
__device__ __align__(16) __nv_bfloat16 g_W2_hi[(size_t)H1 * H2];
__device__ __align__(16) uint8_t       g_W2T_8 [(size_t)H2 * H1];
__device__ __align__(16) uint8_t       g_W2T_8L[(size_t)H2 * H1];
__device__ __align__(16) __nv_bfloat16 g_H_hi[(size_t)SU * H1];       // hidden, reused
__device__ __align__(16) uint8_t       g_H_8 [(size_t)SU * H1];
__device__ __align__(16) uint8_t       g_H_8L[(size_t)SU * H1];
__device__ __align__(16) float g_feat_l[(size_t)SL * H2];
__device__ int g_a[SU];
__device__ int g_b[SU];

// ---------------------------------------------------------------------------
// helpers
// ---------------------------------------------------------------------------
__device__ __forceinline__ uint32_t pk_bf16(__nv_bfloat16 a, __nv_bfloat16 b) {
    return (uint32_t)__bfloat16_as_ushort(a) | ((uint32_t)__bfloat16_as_ushort(b) << 16);
}
__device__ __forceinline__ uint8_t f2e4(float f) {
    __nv_fp8_e4m3 t(f); return reinterpret_cast<uint8_t&>(t);
}
__device__ __forceinline__ uint8_t f2e5(float f) {
    __nv_fp8_e5m2 t(f); return reinterpret_cast<uint8_t&>(t);
}

// fp32 -> bf16 hi + e4m3(v) + e5m2(v - hi), x4 (for X and standalone use)
__global__ void cvt3(const float4* __restrict__ in, uint2* __restrict__ hi,
                     uint32_t* __restrict__ o8, uint32_t* __restrict__ o8l, int n4) {
    int i = blockIdx.x * blockDim.x + threadIdx.x;
    if (i >= n4) return;
    float4 f = in[i];
    __nv_bfloat16 h0 = __float2bfloat16(f.x), h1 = __float2bfloat16(f.y);
    __nv_bfloat16 h2 = __float2bfloat16(f.z), h3 = __float2bfloat16(f.w);
    hi[i] = make_uint2(pk_bf16(h0, h1), pk_bf16(h2, h3));
    o8[i] = (uint32_t)f2e4(f.x) | ((uint32_t)f2e4(f.y) << 8) |
            ((uint32_t)f2e4(f.z) << 16) | ((uint32_t)f2e4(f.w) << 24);
    o8l[i] = (uint32_t)f2e5(f.x - __bfloat162float(h0)) |
             ((uint32_t)f2e5(f.y - __bfloat162float(h1)) << 8) |
             ((uint32_t)f2e5(f.z - __bfloat162float(h2)) << 16) |
             ((uint32_t)f2e5(f.w - __bfloat162float(h3)) << 24);
}

// W [K][N] fp32 -> (x64): Whi bf16 [K][N], WT8 e4m3 [N][K], WT8L e5m2 [N][K]
__global__ void cvt_w(const float* __restrict__ in, __nv_bfloat16* __restrict__ whi,
                      uint8_t* __restrict__ wt8, uint8_t* __restrict__ wt8l,
                      int K, int N) {
    __shared__ float tile[32][33];
    const int n0 = blockIdx.x * 32, k0 = blockIdx.y * 32;
    const int tx = threadIdx.x, ty = threadIdx.y;   // 32 x 8
#pragma unroll
    for (int i = 0; i < 32; i += 8) {
        float v = in[(size_t)(k0 + ty + i) * N + n0 + tx] * 64.0f;
        tile[ty + i][tx] = v;
        whi[(size_t)(k0 + ty + i) * N + n0 + tx] = __float2bfloat16(v);
    }
    __syncthreads();
#pragma unroll
    for (int i = 0; i < 32; i += 8) {
        float v = tile[tx][ty + i];                 // (k0+tx, n0+ty+i)
        __nv_bfloat16 h = __float2bfloat16(v);
        size_t o = (size_t)(n0 + ty + i) * K + k0 + tx;
        wt8[o]  = f2e4(v);
        wt8l[o] = f2e5(v - __bfloat162float(h));
    }
}

__device__ __forceinline__ void ldsm4(uint32_t* r, uint32_t addr) {
    asm volatile("ldmatrix.sync.aligned.m8n8.x4.shared.b16 {%0,%1,%2,%3}, [%4];"
                 : "=r"(r[0]), "=r"(r[1]), "=r"(r[2]), "=r"(r[3]) : "r"(addr));
}
__device__ __forceinline__ void ldsm4t(uint32_t* r, uint32_t addr) {
    asm volatile("ldmatrix.sync.aligned.m8n8.x4.trans.shared.b16 {%0,%1,%2,%3}, [%4];"
                 : "=r"(r[0]), "=r"(r[1]), "=r"(r[2]), "=r"(r[3]) : "r"(addr));
}
__device__ __forceinline__ void mma16816(float* c, const uint32_t* a, const uint32_t* b) {
    asm volatile("mma.sync.aligned.m16n8k16.row.col.f32.bf16.bf16.f32 "
                 "{%0,%1,%2,%3}, {%4,%5,%6,%7}, {%8,%9}, {%0,%1,%2,%3};"
                 : "+f"(c[0]), "+f"(c[1]), "+f"(c[2]), "+f"(c[3])
                 : "r"(a[0]), "r"(a[1]), "r"(a[2]), "r"(a[3]), "r"(b[0]), "r"(b[1]));
}
// fp8 correction mmas, k32, same fp32 accumulator
__device__ __forceinline__ void mma_e4e5(float* c, const uint32_t* a, uint32_t b0, uint32_t b1) {
    asm volatile("mma.sync.aligned.m16n8k32.row.col.f32.e4m3.e5m2.f32 "
                 "{%0,%1,%2,%3}, {%4,%5,%6,%7}, {%8,%9}, {%0,%1,%2,%3};"
                 : "+f"(c[0]), "+f"(c[1]), "+f"(c[2]), "+f"(c[3])
                 : "r"(a[0]), "r"(a[1]), "r"(a[2]), "r"(a[3]), "r"(b0), "r"(b1));
}
__device__ __forceinline__ void mma_e5e4(float* c, const uint32_t* a, uint32_t b0, uint32_t b1) {
    asm volatile("mma.sync.aligned.m16n8k32.row.col.f32.e5m2.e4m3.f32 "
                 "{%0,%1,%2,%3}, {%4,%5,%6,%7}, {%8,%9}, {%0,%1,%2,%3};"
                 : "+f"(c[0]), "+f"(c[1]), "+f"(c[2]), "+f"(c[3])
                 : "r"(a[0]), "r"(a[1]), "r"(a[2]), "r"(a[3]), "r"(b0), "r"(b1));
}
#define CP16(so, gp) \
    asm volatile("cp.async.cg.shared.global [%0], [%1], 16;\n" :: "r"(so), "l"(gp))
#define CP_COMMIT()  asm volatile("cp.async.commit_group;\n" ::: "memory")
#define CP_WAIT0()   asm volatile("cp.async.wait_group 0;\n" ::: "memory")

// ===========================================================================
// GEMM: C = relu((A @ (64*B)) / 64 + bias)
// main: bf16 hi*hi. corrections: e4m3(A)*e5m2(loB) + e5m2(loA)*e4m3(B), k32.
// BM=128, BN=64, BK=64; 8 warps, warp tile 32x32; 2 CTA/SM (R13 geometry).
// stage: A_hi 16KB | A_f8 packed 16KB | B_hi 8KB | B_f8 packed 8KB = 48KB
// ===========================================================================
#define BM 128
#define BN 64
#define BK 64
#define ST_A8 16384
#define ST_BH 32768
#define ST_B8 40960
#define ST_SZ 49152

__global__ __launch_bounds__(256, 2)
void gemm_fp8mix(const __nv_bfloat16* __restrict__ Ahi, const uint8_t* __restrict__ A8,
                 const uint8_t* __restrict__ A8L,
                 const __nv_bfloat16* __restrict__ Bhi,   // [K][N] x64
                 const uint8_t* __restrict__ BT8,         // [N][K] x64
                 const uint8_t* __restrict__ BT8L,
                 const float* __restrict__ bias,
                 float* __restrict__ Cf,
                 __nv_bfloat16* __restrict__ Chi, uint8_t* __restrict__ C8,
                 uint8_t* __restrict__ C8L,
                 int M, int N, int K) {
    extern __shared__ char sm[];
    const int tid  = threadIdx.x;
    const int lane = tid & 31;
    const int wid  = tid >> 5;
    const int wm   = (wid >> 1) * 32;
    const int wn   = (wid & 1) * 32;
    const int bm   = blockIdx.y * BM;
    const int bn   = blockIdx.x * BN;

    const uint32_t smBase = (uint32_t)__cvta_generic_to_shared(sm);

    float acc[2][4][4];
#pragma unroll
    for (int i = 0; i < 2; i++)
#pragma unroll
        for (int j = 0; j < 4; j++)
#pragma unroll
            for (int v = 0; v < 4; v++) acc[i][j][v] = 0.0f;

    auto load_stage = [&](int kt, int stg) {
        const uint32_t base = smBase + stg * ST_SZ;
        const size_t a0 = (size_t)bm * K + (size_t)kt * BK;
        const size_t b0 = (size_t)kt * BK * N + bn;
        const size_t bt0 = (size_t)bn * K + (size_t)kt * BK;
#pragma unroll
        for (int p = 0; p < 4; ++p) {   // A hi bf16: 128 rows x 8 chunks
            const int c = tid + p * 256;
            const int r = c >> 3, ch = c & 7;
            const uint32_t so = base + r * 128 + (((ch ^ (r & 7)) & 7) << 4);
            CP16(so, Ahi + a0 + (size_t)r * K + ch * 8);
        }
#pragma unroll
        for (int p = 0; p < 4; ++p) {   // A fp8 packed: chunks 0-3 = A8, 4-7 = A8L
            const int c = tid + p * 256;
            const int r = c >> 3, ch = c & 7;
            const uint32_t so = base + ST_A8 + r * 128 + (((ch ^ (r & 7)) & 7) << 4);
            const uint8_t* src = (ch < 4) ? (A8  + a0 + (size_t)r * K + ch * 16)
                                          : (A8L + a0 + (size_t)r * K + (ch - 4) * 16);
            CP16(so, src);
        }
#pragma unroll
        for (int p = 0; p < 2; ++p) {   // B hi bf16 [K][N]: 64 k-rows x 8 chunks
            const int c = tid + p * 256;
            const int k = c >> 3, ch = c & 7;
            const uint32_t so = base + ST_BH + k * 128 + (((ch ^ (k & 7)) & 7) << 4);
            CP16(so, Bhi + b0 + (size_t)k * N + ch * 8);
        }
#pragma unroll
        for (int p = 0; p < 2; ++p) {   // B fp8 packed [N][K]: 64 n-rows x 8 chunks
            const int c = tid + p * 256;
            const int nr = c >> 3, ch = c & 7;
            const uint32_t so = base + ST_B8 + nr * 128 + (((ch ^ (nr & 7)) & 7) << 4);
            const uint8_t* src = (ch < 4) ? (BT8  + bt0 + (size_t)nr * K + ch * 16)
                                          : (BT8L + bt0 + (size_t)nr * K + (ch - 4) * 16);
            CP16(so, src);
        }
        CP_COMMIT();
    };

    const int NT = K / BK;
    load_stage(0, 0);

    int stg = 0;
    for (int t = 0; t < NT; ++t) {
        CP_WAIT0();
        __syncthreads();
        if (t + 1 < NT) load_stage(t + 1, stg ^ 1);

        const uint32_t sb = smBase + stg * ST_SZ;

        // ---- bf16 hi*hi ----
#pragma unroll
        for (int ks = 0; ks < 4; ++ks) {
            const int k16 = ks * 16;
            uint32_t ah[2][4], bh[2][4];
#pragma unroll
            for (int mt = 0; mt < 2; ++mt) {
                const int r  = wm + mt * 16 + (lane & 15);
                const int kc = k16 + (lane >> 4) * 8;
                const uint32_t ad = sb + r * 128 + ((((kc >> 3) ^ (r & 7)) & 7) << 4);
                ldsm4(ah[mt], ad);
            }
#pragma unroll
            for (int j = 0; j < 2; ++j) {
                const int kl = k16 + (lane & 15);
                const int nl = wn + j * 16 + (lane >> 4) * 8;
                const uint32_t bd = sb + ST_BH + kl * 128 + ((((nl >> 3) ^ (kl & 7)) & 7) << 4);
                ldsm4t(bh[j], bd);
            }
#pragma unroll
            for (int mt = 0; mt < 2; ++mt)
#pragma unroll
                for (int nt = 0; nt < 4; ++nt) {
                    const int j = nt >> 1, s = (nt & 1) * 2;
                    mma16816(acc[mt][nt], ah[mt], &bh[j][s]);
                }
        }

        // ---- fp8 corrections (k32) ----
#pragma unroll
        for (int ks2 = 0; ks2 < 2; ++ks2) {
            uint32_t a8[2][4], a8l[2][4];
#pragma unroll
            for (int mt = 0; mt < 2; ++mt) {
                const int r  = wm + mt * 16 + (lane & 15);
                const int cA = ks2 * 2 + (lane >> 4);   // 0..3
                const uint32_t base = sb + ST_A8 + r * 128;
                ldsm4(a8[mt],  base + ((((cA)     ^ (r & 7)) & 7) << 4));
                ldsm4(a8l[mt], base + ((((cA + 4) ^ (r & 7)) & 7) << 4));
            }
            uint32_t b8a[4], b8b[4], b8la[4], b8lb[4];
            {
                const int nrA = wn + ((lane >> 3) & 1) * 8 + (lane & 7);   // groups 0,1
                const int nrB = nrA + 16;                                  // groups 2,3
                const int cB = ks2 * 2 + (lane >> 4);
                const uint32_t baseA = sb + ST_B8 + nrA * 128;
                const uint32_t baseB = sb + ST_B8 + nrB * 128;
                ldsm4(b8a,  baseA + ((((cB)     ^ (nrA & 7)) & 7) << 4));
                ldsm4(b8la, baseA + ((((cB + 4) ^ (nrA & 7)) & 7) << 4));
                ldsm4(b8b,  baseB + ((((cB)     ^ (nrB & 7)) & 7) << 4));
                ldsm4(b8lb, baseB + ((((cB + 4) ^ (nrB & 7)) & 7) << 4));
            }
#pragma unroll
            for (int mt = 0; mt < 2; ++mt) {
                mma_e4e5(acc[mt][0], a8[mt],  b8la[0], b8la[2]);
                mma_e5e4(acc[mt][0], a8l[mt], b8a[0],  b8a[2]);
                mma_e4e5(acc[mt][1], a8[mt],  b8la[1], b8la[3]);
                mma_e5e4(acc[mt][1], a8l[mt], b8a[1],  b8a[3]);
                mma_e4e5(acc[mt][2], a8[mt],  b8lb[0], b8lb[2]);
                mma_e5e4(acc[mt][2], a8l[mt], b8b[0],  b8b[2]);
                mma_e4e5(acc[mt][3], a8[mt],  b8lb[1], b8lb[3]);
                mma_e5e4(acc[mt][3], a8l[mt], b8b[1],  b8b[3]);
            }
        }
        __syncthreads();
        stg ^= 1;
    }

    // Epilogue: v = acc/64 + bias, relu
#pragma unroll
    for (int nt = 0; nt < 4; ++nt) {
        const int cn = bn + wn + nt * 8 + (lane & 3) * 2;
        const float2 bv = *(const float2*)(bias + cn);
#pragma unroll
        for (int mt = 0; mt < 2; ++mt) {
            const int r0 = bm + wm + mt * 16 + (lane >> 2);
            float v[2][2];
            v[0][0] = fmaxf(acc[mt][nt][0] * INV64 + bv.x, 0.0f);
            v[0][1] = fmaxf(acc[mt][nt][1] * INV64 + bv.y, 0.0f);
            v[1][0] = fmaxf(acc[mt][nt][2] * INV64 + bv.x, 0.0f);
            v[1][1] = fmaxf(acc[mt][nt][3] * INV64 + bv.y, 0.0f);
#pragma unroll
            for (int h = 0; h < 2; ++h) {
                const size_t idx = (size_t)(r0 + h * 8) * N + cn;
                if (Cf) *(float2*)(Cf + idx) = make_float2(v[h][0], v[h][1]);
                if (Chi) {
                    __nv_bfloat16 h0 = __float2bfloat16(v[h][0]);
                    __nv_bfloat16 h1 = __float2bfloat16(v[h][1]);
                    *(uint32_t*)(Chi + idx) = pk_bf16(h0, h1);
                    *(uint16_t*)(C8 + idx) =
                        (uint16_t)f2e4(v[h][0]) | ((uint16_t)f2e4(v[h][1]) << 8);
                    *(uint16_t*)(C8L + idx) =
                        (uint16_t)f2e5(v[h][0] - __bfloat162float(h0)) |
                        ((uint16_t)f2e5(v[h][1] - __bfloat162float(h1)) << 8);
                }
            }
        }
    }
}

// ---------------------------------------------------------------------------
// y_hat[r] = dot(feat_l[r,:], W3) + b3   (one warp per row)
// ---------------------------------------------------------------------------
__global__ void yhat_kernel(const float* __restrict__ feat_l,
                            const float* __restrict__ W3,
                            const float* __restrict__ b3,
                            float* __restrict__ out) {
    int warp = (blockIdx.x * blockDim.x + threadIdx.x) >> 5;
    int lane = threadIdx.x & 31;
    if (warp >= SL) return;
    const float* row = feat_l + (size_t)warp * H2;
    float s = 0.0f;
#pragma unroll
    for (int d = lane; d < H2; d += 32) s += row[d] * W3[d];
#pragma unroll
    for (int off = 16; off > 0; off >>= 1)
        s += __shfl_down_sync(0xFFFFFFFFu, s, off);
    if (lane == 0) out[warp] = s + b3[0];
}

// ---------------------------------------------------------------------------
// JAX threefry2x32 (20 rounds)
// ---------------------------------------------------------------------------
__device__ __forceinline__ uint32_t rotl32(uint32_t v, int d) {
    return (v << d) | (v >> (32 - d));
}
__device__ __forceinline__ void threefry2x32(uint32_t k0, uint32_t k1,
                                             uint32_t x0, uint32_t x1,
                                             uint32_t& o0, uint32_t& o1) {
    uint32_t k2 = k0 ^ k1 ^ 0x1BD11BDAu;
    x0 += k0; x1 += k1;
#define TF_RND(r) { x0 += x1; x1 = rotl32(x1, r); x1 ^= x0; }
    TF_RND(13) TF_RND(15) TF_RND(26) TF_RND(6)
    x0 += k1; x1 += k2 + 1u;
    TF_RND(17) TF_RND(29) TF_RND(16) TF_RND(24)
    x0 += k2; x1 += k0 + 2u;
    TF_RND(13) TF_RND(15) TF_RND(26) TF_RND(6)
    x0 += k0; x1 += k1 + 3u;
    TF_RND(17) TF_RND(29) TF_RND(16) TF_RND(24)
    x0 += k1; x1 += k2 + 4u;
    TF_RND(13) TF_RND(15) TF_RND(26) TF_RND(6)
    x0 += k2; x1 += k0 + 5u;
#undef TF_RND
    o0 = x0; o1 = x1;
}

// ---------------------------------------------------------------------------
// Pair sampling — JAX partitionable threefry (verified PASS R9/R11/R13/R15)
// ---------------------------------------------------------------------------
__global__ void sample_pairs_kernel(const float* __restrict__ y_l,
                                    int* __restrict__ a_out,
                                    int* __restrict__ b_out) {
    int s = blockIdx.x * blockDim.x + threadIdx.x;
    if (s >= SU) return;

    uint32_t o0, o1;
    uint32_t ka0, ka1, kb0, kb1;
    threefry2x32(0u, 42u, 0u, 0u, ka0, ka1);
    threefry2x32(0u, 42u, 0u, 1u, kb0, kb1);

    uint32_t ka2_0, ka2_1, kb2_0, kb2_1;
    threefry2x32(ka0, ka1, 0u, 1u, ka2_0, ka2_1);
    threefry2x32(kb0, kb1, 0u, 1u, kb2_0, kb2_1);

    int a = -1, b = -1, a_first = 0, b_first = 0;
#pragma unroll
    for (int k = 0; k < K_TRIES; k++) {
        uint32_t i = (uint32_t)s * K_TRIES + k;
        threefry2x32(ka2_0, ka2_1, 0u, i, o0, o1);
        int ia = (int)((o0 ^ o1) & (SL - 1));
        threefry2x32(kb2_0, kb2_1, 0u, i, o0, o1);
        int ib = (int)((o0 ^ o1) & (SL - 1));
        if (k == 0) { a_first = ia; b_first = ib; }
        if (a < 0 && ia != ib && y_l[ia] != y_l[ib]) { a = ia; b = ib; }
    }
    if (a < 0) { a = a_first; b = b_first; }
    a_out[s] = a;
    b_out[s] = b;
}

// ---------------------------------------------------------------------------
// feat_comb[s] = k * feat_l[a] + (1-k) * feat_l[b]
// ---------------------------------------------------------------------------
__global__ void combine_kernel(const float* __restrict__ feat_l,
                               const float* __restrict__ y_l,
                               const float* __restrict__ y_u,
                               const int* __restrict__ a_idx,
                               const int* __restrict__ b_idx,
                               float* __restrict__ out) {
    int s = blockIdx.x;
    int a = a_idx[s], b = b_idx[s];
    float ya = y_l[a], yb = y_l[b];
    float kc = (y_u[s] - yb) / (ya - yb);
    float km = 1.0f - kc;
    const float4* fa = (const float4*)(feat_l + (size_t)a * H2);
    const float4* fb = (const float4*)(feat_l + (size_t)b * H2);
    float4* o = (float4*)(out + (size_t)s * H2);
    for (int d = threadIdx.x; d < H2 / 4; d += blockDim.x) {
        float4 va = fa[d], vb = fb[d], r;
        r.x = kc * va.x + km * vb.x;
        r.y = kc * va.y + km * vb.y;
        r.z = kc * va.z + km * vb.z;
        r.w = kc * va.w + km * vb.w;
        o[d] = r;
    }
}

// ---------------------------------------------------------------------------
// Launch
// ---------------------------------------------------------------------------
extern "C" void kernel_launch(void* const* d_in, const int* in_sizes, int n_in,
                              void* d_out, int out_size) {
    const float* X_l = (const float*)d_in[0];
    const float* y_l = (const float*)d_in[1];
    const float* X_u = (const float*)d_in[2];
    const float* y_u = (const float*)d_in[3];
    const float* W1  = (const float*)d_in[4];
    const float* b1  = (const float*)d_in[5];
    const float* W2  = (const float*)d_in[6];
    const float* b2  = (const float*)d_in[7];
    const float* W3  = (const float*)d_in[8];
    const float* b3  = (const float*)d_in[9];

    float* out = (float*)d_out;
    float* out_feat_u    = out;                       // [SU, H2]
    float* out_feat_comb = out + (size_t)SU * H2;     // [SU, H2]
    float* out_yhat      = out + (size_t)2 * SU * H2; // [SL, 1]

    __nv_bfloat16 *pXuh, *pXlh, *pW1h, *pW2h, *pHh;
    uint8_t *pXu8, *pXu8L, *pXl8, *pXl8L, *pW1T8, *pW1T8L, *pW2T8, *pW2T8L, *pH8, *pH8L;
    float* pfl;
    int *pa, *pb;
    cudaGetSymbolAddress((void**)&pXuh,  g_Xu_hi);
    cudaGetSymbolAddress((void**)&pXu8,  g_Xu_8);
    cudaGetSymbolAddress((void**)&pXu8L, g_Xu_8L);
    cudaGetSymbolAddress((void**)&pXlh,  g_Xl_hi);
    cudaGetSymbolAddress((void**)&pXl8,  g_Xl_8);
    cudaGetSymbolAddress((void**)&pXl8L, g_Xl_8L);
    cudaGetSymbolAddress((void**)&pW1h,  g_W1_hi);
    cudaGetSymbolAddress((void**)&pW1T8, g_W1T_8);
    cudaGetSymbolAddress((void**)&pW1T8L,g_W1T_8L);
    cudaGetSymbolAddress((void**)&pW2h,  g_W2_hi);
    cudaGetSymbolAddress((void**)&pW2T8, g_W2T_8);
    cudaGetSymbolAddress((void**)&pW2T8L,g_W2T_8L);
    cudaGetSymbolAddress((void**)&pHh,   g_H_hi);
    cudaGetSymbolAddress((void**)&pH8,   g_H_8);
    cudaGetSymbolAddress((void**)&pH8L,  g_H_8L);
    cudaGetSymbolAddress((void**)&pfl,   g_feat_l);
    cudaGetSymbolAddress((void**)&pa,    g_a);
    cudaGetSymbolAddress((void**)&pb,    g_b);

    cudaFuncSetAttribute(gemm_fp8mix,
                         cudaFuncAttributeMaxDynamicSharedMemorySize, 2 * ST_SZ);

    // --- one-time converts
    {
        int n4 = SU * DIM_X / 4;
        cvt3<<<(n4 + 255) / 256, 256>>>((const float4*)X_u, (uint2*)pXuh,
                                        (uint32_t*)pXu8, (uint32_t*)pXu8L, n4);
        n4 = SL * DIM_X / 4;
        cvt3<<<(n4 + 255) / 256, 256>>>((const float4*)X_l, (uint2*)pXlh,
                                        (uint32_t*)pXl8, (uint32_t*)pXl8L, n4);
    }
    cvt_w<<<dim3(H1 / 32, DIM_X / 32), dim3(32, 8)>>>(W1, pW1h, pW1T8, pW1T8L, DIM_X, H1);
    cvt_w<<<dim3(H2 / 32, H1 / 32),    dim3(32, 8)>>>(W2, pW2h, pW2T8, pW2T8L, H1, H2);

    // --- unlabeled branch
    gemm_fp8mix<<<dim3(H1 / BN, SU / BM), 256, 2 * ST_SZ>>>(
        pXuh, pXu8, pXu8L, pW1h, pW1T8, pW1T8L, b1,
        nullptr, pHh, pH8, pH8L, SU, H1, DIM_X);
    gemm_fp8mix<<<dim3(H2 / BN, SU / BM), 256, 2 * ST_SZ>>>(
        pHh, pH8, pH8L, pW2h, pW2T8, pW2T8L, b2,
        out_feat_u, nullptr, nullptr, nullptr, SU, H2, H1);

    // --- labeled branch (reuses g_H)
    gemm_fp8mix<<<dim3(H1 / BN, SL / BM), 256, 2 * ST_SZ>>>(
        pXlh, pXl8, pXl8L, pW1h, pW1T8, pW1T8L, b1,
        nullptr, pHh, pH8, pH8L, SL, H1, DIM_X);
    gemm_fp8mix<<<dim3(H2 / BN, SL / BM), 256, 2 * ST_SZ>>>(
        pHh, pH8, pH8L, pW2h, pW2T8, pW2T8L, b2,
        pfl, nullptr, nullptr, nullptr, SL, H2, H1);

    // --- y_hat
    yhat_kernel<<<SL / 8, 256>>>(pfl, W3, b3, out_yhat);

    // --- pair sampling + combine
    sample_pairs_kernel<<<SU / 256, 256>>>(y_l, pa, pb);
    combine_kernel<<<SU, 128>>>(pfl, y_l, y_u, pa, pb, out_feat_comb);
}

// round 17
// speedup vs baseline: 1.3844x; 1.3844x over previous
#include <cuda_runtime.h>
#include <cuda_bf16.h>
#include <cstdint>

// Problem constants
#define DIM_X 1024
#define H1    2048
#define H2    512
#define SL    8192
#define SU    16384
#define MT    (SU + SL)      // merged batch rows = 24576
#define K_TRIES 8

// ---------------------------------------------------------------------------
// Device scratch (no allocations allowed). 16B-aligned for cp.async.
// X and H are MERGED: rows [0,SU) = unlabeled, rows [SU,MT) = labeled.
// ---------------------------------------------------------------------------
__device__ __align__(16) __nv_bfloat16 g_X_hi[(size_t)MT * DIM_X];
__device__ __align__(16) __nv_bfloat16 g_X_lo[(size_t)MT * DIM_X];
__device__ __align__(16) __nv_bfloat16 g_W1_hi[(size_t)DIM_X * H1];
__device__ __align__(16) __nv_bfloat16 g_W1_lo[(size_t)DIM_X * H1];
__device__ __align__(16) __nv_bfloat16 g_W2_hi[(size_t)H1 * H2];
__device__ __align__(16) __nv_bfloat16 g_W2_lo[(size_t)H1 * H2];
__device__ __align__(16) __nv_bfloat16 g_H_hi[(size_t)MT * H1];
__device__ __align__(16) __nv_bfloat16 g_H_lo[(size_t)MT * H1];
__device__ __align__(16) float g_feat_l[(size_t)SL * H2];
__device__ int g_a[SU];
__device__ int g_b[SU];

// ---------------------------------------------------------------------------
// helpers
// ---------------------------------------------------------------------------
__device__ __forceinline__ uint32_t pk_bf16(__nv_bfloat16 a, __nv_bfloat16 b) {
    return (uint32_t)__bfloat16_as_ushort(a) | ((uint32_t)__bfloat16_as_ushort(b) << 16);
}

// fp32 -> (hi, lo) bf16 split, vectorized x4
__global__ void cvt_hilo(const float4* __restrict__ in, uint2* __restrict__ hi,
                         uint2* __restrict__ lo, int n4) {
    int i = blockIdx.x * blockDim.x + threadIdx.x;
    if (i >= n4) return;
    float4 f = in[i];
    __nv_bfloat16 h0 = __float2bfloat16(f.x), h1 = __float2bfloat16(f.y);
    __nv_bfloat16 h2 = __float2bfloat16(f.z), h3 = __float2bfloat16(f.w);
    __nv_bfloat16 l0 = __float2bfloat16(f.x - __bfloat162float(h0));
    __nv_bfloat16 l1 = __float2bfloat16(f.y - __bfloat162float(h1));
    __nv_bfloat16 l2 = __float2bfloat16(f.z - __bfloat162float(h2));
    __nv_bfloat16 l3 = __float2bfloat16(f.w - __bfloat162float(h3));
    hi[i] = make_uint2(pk_bf16(h0, h1), pk_bf16(h2, h3));
    lo[i] = make_uint2(pk_bf16(l0, l1), pk_bf16(l2, l3));
}

__device__ __forceinline__ void ldsm4(uint32_t* r, uint32_t addr) {
    asm volatile("ldmatrix.sync.aligned.m8n8.x4.shared.b16 {%0,%1,%2,%3}, [%4];"
                 : "=r"(r[0]), "=r"(r[1]), "=r"(r[2]), "=r"(r[3]) : "r"(addr));
}
__device__ __forceinline__ void ldsm4t(uint32_t* r, uint32_t addr) {
    asm volatile("ldmatrix.sync.aligned.m8n8.x4.trans.shared.b16 {%0,%1,%2,%3}, [%4];"
                 : "=r"(r[0]), "=r"(r[1]), "=r"(r[2]), "=r"(r[3]) : "r"(addr));
}
__device__ __forceinline__ void mma16816(float* c, const uint32_t* a, const uint32_t* b) {
    asm volatile("mma.sync.aligned.m16n8k16.row.col.f32.bf16.bf16.f32 "
                 "{%0,%1,%2,%3}, {%4,%5,%6,%7}, {%8,%9}, {%0,%1,%2,%3};"
                 : "+f"(c[0]), "+f"(c[1]), "+f"(c[2]), "+f"(c[3])
                 : "r"(a[0]), "r"(a[1]), "r"(a[2]), "r"(a[3]), "r"(b[0]), "r"(b[1]));
}
#define CP16(so, gp) \
    asm volatile("cp.async.cg.shared.global [%0], [%1], 16;\n" :: "r"(so), "l"(gp))
#define CP_COMMIT()  asm volatile("cp.async.commit_group;\n" ::: "memory")
#define CP_WAIT0()   asm volatile("cp.async.wait_group 0;\n" ::: "memory")

// ===========================================================================
// Tensor-core GEMM on pre-split bf16 operands (R13-verified hot path):
//   C = relu(A @ B + bias)
// bf16x3: hi*hi + hi*lo + lo*hi, fp32 accumulate.
// BM=128, BN=64, BK=64; 8 warps, warp tile 32x32; 2 CTA/SM; cp.async 2-stage.
// fp32 output: rows < MU -> CfU, rows >= MU -> CfL (shifted) — both optional.
// bf16 hi/lo output (Chi/Clo) optional, contiguous over full M.
// ===========================================================================
#define BM 128
#define BN 64
#define BK 64
#define ST_ALO 16384
#define ST_BHI 32768
#define ST_BLO 40960
#define ST_SZ  49152

__global__ __launch_bounds__(256, 2)
void gemm_bf16x3(const __nv_bfloat16* __restrict__ Ahi, const __nv_bfloat16* __restrict__ Alo,
                 const __nv_bfloat16* __restrict__ Bhi, const __nv_bfloat16* __restrict__ Blo,
                 const float* __restrict__ bias,
                 float* __restrict__ CfU, float* __restrict__ CfL, int MU,
                 __nv_bfloat16* __restrict__ Chi, __nv_bfloat16* __restrict__ Clo,
                 int M, int N, int K) {
    extern __shared__ char sm[];
    const int tid  = threadIdx.x;
    const int lane = tid & 31;
    const int wid  = tid >> 5;
    const int wm   = (wid >> 1) * 32;
    const int wn   = (wid & 1) * 32;
    const int bm   = blockIdx.y * BM;
    const int bn   = blockIdx.x * BN;

    const uint32_t smBase = (uint32_t)__cvta_generic_to_shared(sm);

    float acc[2][4][4];
#pragma unroll
    for (int i = 0; i < 2; i++)
#pragma unroll
        for (int j = 0; j < 4; j++)
#pragma unroll
            for (int v = 0; v < 4; v++) acc[i][j][v] = 0.0f;

    auto load_stage = [&](int kt, int stg) {
        const uint32_t base = smBase + stg * ST_SZ;
        const size_t a0 = (size_t)bm * K + (size_t)kt * BK;
        const size_t b0 = (size_t)kt * BK * N + bn;
#pragma unroll
        for (int p = 0; p < 4; ++p) {              // A: 128 rows x 8 chunks (x2 for hi/lo)
            const int c = tid + p * 256;
            const int r = c >> 3, ch = c & 7;
            const uint32_t so = base + r * 128 + (((ch ^ (r & 7)) & 7) << 4);
            const size_t g = a0 + (size_t)r * K + ch * 8;
            CP16(so, Ahi + g);
            CP16(so + ST_ALO, Alo + g);
        }
#pragma unroll
        for (int p = 0; p < 2; ++p) {              // B: 64 rows x 8 chunks (x2)
            const int c = tid + p * 256;
            const int k = c >> 3, ch = c & 7;
            const uint32_t so = base + ST_BHI + k * 128 + (((ch ^ (k & 7)) & 7) << 4);
            const size_t g = b0 + (size_t)k * N + ch * 8;
            CP16(so, Bhi + g);
            CP16(so + (ST_BLO - ST_BHI), Blo + g);
        }
        CP_COMMIT();
    };

    const int NT = K / BK;
    load_stage(0, 0);

    int stg = 0;
    for (int t = 0; t < NT; ++t) {
        CP_WAIT0();
        __syncthreads();
        if (t + 1 < NT) load_stage(t + 1, stg ^ 1);

        const uint32_t sb = smBase + stg * ST_SZ;
#pragma unroll
        for (int ks = 0; ks < 4; ++ks) {
            const int k16 = ks * 16;
            uint32_t ah[2][4], al[2][4], bh[2][4], bl[2][4];
#pragma unroll
            for (int mt = 0; mt < 2; ++mt) {
                const int r  = wm + mt * 16 + (lane & 15);
                const int kc = k16 + (lane >> 4) * 8;
                const uint32_t ad = sb + r * 128 + ((((kc >> 3) ^ (r & 7)) & 7) << 4);
                ldsm4(ah[mt], ad);
                ldsm4(al[mt], ad + ST_ALO);
            }
#pragma unroll
            for (int j = 0; j < 2; ++j) {
                const int kl = k16 + (lane & 15);
                const int nl = wn + j * 16 + (lane >> 4) * 8;
                const uint32_t bd = sb + ST_BHI + kl * 128 + ((((nl >> 3) ^ (kl & 7)) & 7) << 4);
                ldsm4t(bh[j], bd);
                ldsm4t(bl[j], bd + (ST_BLO - ST_BHI));
            }
#pragma unroll
            for (int mt = 0; mt < 2; ++mt)
#pragma unroll
                for (int nt = 0; nt < 4; ++nt) {
                    const int j = nt >> 1, s = (nt & 1) * 2;
                    mma16816(acc[mt][nt], ah[mt], &bh[j][s]);   // hi*hi
                    mma16816(acc[mt][nt], ah[mt], &bl[j][s]);   // hi*lo
                    mma16816(acc[mt][nt], al[mt], &bh[j][s]);   // lo*hi
                }
        }
        __syncthreads();
        stg ^= 1;
    }

    // Epilogue: bias + relu; fp32 (routed u/l) and/or bf16 hi/lo stores
    const bool isU = (bm < MU);
    float* Cf = isU ? CfU : CfL;
    const int rowShift = isU ? 0 : MU;
#pragma unroll
    for (int nt = 0; nt < 4; ++nt) {
        const int cn = bn + wn + nt * 8 + (lane & 3) * 2;
        const float2 bv = *(const float2*)(bias + cn);
#pragma unroll
        for (int mt = 0; mt < 2; ++mt) {
            const int r0 = bm + wm + mt * 16 + (lane >> 2);
            float v[2][2];
            v[0][0] = fmaxf(acc[mt][nt][0] + bv.x, 0.0f);
            v[0][1] = fmaxf(acc[mt][nt][1] + bv.y, 0.0f);
            v[1][0] = fmaxf(acc[mt][nt][2] + bv.x, 0.0f);
            v[1][1] = fmaxf(acc[mt][nt][3] + bv.y, 0.0f);
#pragma unroll
            for (int h = 0; h < 2; ++h) {
                const int rr = r0 + h * 8;
                if (Cf) {
                    const size_t idx = (size_t)(rr - rowShift) * N + cn;
                    *(float2*)(Cf + idx) = make_float2(v[h][0], v[h][1]);
                }
                if (Chi) {
                    const size_t idx = (size_t)rr * N + cn;
                    __nv_bfloat16 h0 = __float2bfloat16(v[h][0]);
                    __nv_bfloat16 h1 = __float2bfloat16(v[h][1]);
                    __nv_bfloat16 l0 = __float2bfloat16(v[h][0] - __bfloat162float(h0));
                    __nv_bfloat16 l1 = __float2bfloat16(v[h][1] - __bfloat162float(h1));
                    *(uint32_t*)(Chi + idx) = pk_bf16(h0, h1);
                    *(uint32_t*)(Clo + idx) = pk_bf16(l0, l1);
                }
            }
        }
    }
}

// ---------------------------------------------------------------------------
// y_hat[r] = dot(feat_l[r,:], W3) + b3   (one warp per row)
// ---------------------------------------------------------------------------
__global__ void yhat_kernel(const float* __restrict__ feat_l,
                            const float* __restrict__ W3,
                            const float* __restrict__ b3,
                            float* __restrict__ out) {
    int warp = (blockIdx.x * blockDim.x + threadIdx.x) >> 5;
    int lane = threadIdx.x & 31;
    if (warp >= SL) return;
    const float* row = feat_l + (size_t)warp * H2;
    float s = 0.0f;
#pragma unroll
    for (int d = lane; d < H2; d += 32) s += row[d] * W3[d];
#pragma unroll
    for (int off = 16; off > 0; off >>= 1)
        s += __shfl_down_sync(0xFFFFFFFFu, s, off);
    if (lane == 0) out[warp] = s + b3[0];
}

// ---------------------------------------------------------------------------
// JAX threefry2x32 (20 rounds)
// ---------------------------------------------------------------------------
__device__ __forceinline__ uint32_t rotl32(uint32_t v, int d) {
    return (v << d) | (v >> (32 - d));
}
__device__ __forceinline__ void threefry2x32(uint32_t k0, uint32_t k1,
                                             uint32_t x0, uint32_t x1,
                                             uint32_t& o0, uint32_t& o1) {
    uint32_t k2 = k0 ^ k1 ^ 0x1BD11BDAu;
    x0 += k0; x1 += k1;
#define TF_RND(r) { x0 += x1; x1 = rotl32(x1, r); x1 ^= x0; }
    TF_RND(13) TF_RND(15) TF_RND(26) TF_RND(6)
    x0 += k1; x1 += k2 + 1u;
    TF_RND(17) TF_RND(29) TF_RND(16) TF_RND(24)
    x0 += k2; x1 += k0 + 2u;
    TF_RND(13) TF_RND(15) TF_RND(26) TF_RND(6)
    x0 += k0; x1 += k1 + 3u;
    TF_RND(17) TF_RND(29) TF_RND(16) TF_RND(24)
    x0 += k1; x1 += k2 + 4u;
    TF_RND(13) TF_RND(15) TF_RND(26) TF_RND(6)
    x0 += k2; x1 += k0 + 5u;
#undef TF_RND
    o0 = x0; o1 = x1;
}

// ---------------------------------------------------------------------------
// Pair sampling — JAX partitionable threefry (verified PASS R9/R11/R13/R15/R16)
// ---------------------------------------------------------------------------
__global__ void sample_pairs_kernel(const float* __restrict__ y_l,
                                    int* __restrict__ a_out,
                                    int* __restrict__ b_out) {
    int s = blockIdx.x * blockDim.x + threadIdx.x;
    if (s >= SU) return;

    uint32_t o0, o1;
    uint32_t ka0, ka1, kb0, kb1;
    threefry2x32(0u, 42u, 0u, 0u, ka0, ka1);
    threefry2x32(0u, 42u, 0u, 1u, kb0, kb1);

    uint32_t ka2_0, ka2_1, kb2_0, kb2_1;
    threefry2x32(ka0, ka1, 0u, 1u, ka2_0, ka2_1);
    threefry2x32(kb0, kb1, 0u, 1u, kb2_0, kb2_1);

    int a = -1, b = -1, a_first = 0, b_first = 0;
#pragma unroll
    for (int k = 0; k < K_TRIES; k++) {
        uint32_t i = (uint32_t)s * K_TRIES + k;
        threefry2x32(ka2_0, ka2_1, 0u, i, o0, o1);
        int ia = (int)((o0 ^ o1) & (SL - 1));
        threefry2x32(kb2_0, kb2_1, 0u, i, o0, o1);
        int ib = (int)((o0 ^ o1) & (SL - 1));
        if (k == 0) { a_first = ia; b_first = ib; }
        if (a < 0 && ia != ib && y_l[ia] != y_l[ib]) { a = ia; b = ib; }
    }
    if (a < 0) { a = a_first; b = b_first; }
    a_out[s] = a;
    b_out[s] = b;
}

// ---------------------------------------------------------------------------
// feat_comb[s] = k * feat_l[a] + (1-k) * feat_l[b]
// ---------------------------------------------------------------------------
__global__ void combine_kernel(const float* __restrict__ feat_l,
                               const float* __restrict__ y_l,
                               const float* __restrict__ y_u,
                               const int* __restrict__ a_idx,
                               const int* __restrict__ b_idx,
                               float* __restrict__ out) {
    int s = blockIdx.x;
    int a = a_idx[s], b = b_idx[s];
    float ya = y_l[a], yb = y_l[b];
    float kc = (y_u[s] - yb) / (ya - yb);
    float km = 1.0f - kc;
    const float4* fa = (const float4*)(feat_l + (size_t)a * H2);
    const float4* fb = (const float4*)(feat_l + (size_t)b * H2);
    float4* o = (float4*)(out + (size_t)s * H2);
    for (int d = threadIdx.x; d < H2 / 4; d += blockDim.x) {
        float4 va = fa[d], vb = fb[d], r;
        r.x = kc * va.x + km * vb.x;
        r.y = kc * va.y + km * vb.y;
        r.z = kc * va.z + km * vb.z;
        r.w = kc * va.w + km * vb.w;
        o[d] = r;
    }
}

// ---------------------------------------------------------------------------
// Launch
// ---------------------------------------------------------------------------
extern "C" void kernel_launch(void* const* d_in, const int* in_sizes, int n_in,
                              void* d_out, int out_size) {
    const float* X_l = (const float*)d_in[0];
    const float* y_l = (const float*)d_in[1];
    const float* X_u = (const float*)d_in[2];
    const float* y_u = (const float*)d_in[3];
    const float* W1  = (const float*)d_in[4];
    const float* b1  = (const float*)d_in[5];
    const float* W2  = (const float*)d_in[6];
    const float* b2  = (const float*)d_in[7];
    const float* W3  = (const float*)d_in[8];
    const float* b3  = (const float*)d_in[9];

    float* out = (float*)d_out;
    float* out_feat_u    = out;                       // [SU, H2]
    float* out_feat_comb = out + (size_t)SU * H2;     // [SU, H2]
    float* out_yhat      = out + (size_t)2 * SU * H2; // [SL, 1]

    __nv_bfloat16 *pXh, *pXl, *pW1h, *pW1l, *pW2h, *pW2l, *pHh, *pHl;
    float* pfl;
    int *pa, *pb;
    cudaGetSymbolAddress((void**)&pXh,  g_X_hi);
    cudaGetSymbolAddress((void**)&pXl,  g_X_lo);
    cudaGetSymbolAddress((void**)&pW1h, g_W1_hi);
    cudaGetSymbolAddress((void**)&pW1l, g_W1_lo);
    cudaGetSymbolAddress((void**)&pW2h, g_W2_hi);
    cudaGetSymbolAddress((void**)&pW2l, g_W2_lo);
    cudaGetSymbolAddress((void**)&pHh,  g_H_hi);
    cudaGetSymbolAddress((void**)&pHl,  g_H_lo);
    cudaGetSymbolAddress((void**)&pfl,  g_feat_l);
    cudaGetSymbolAddress((void**)&pa,   g_a);
    cudaGetSymbolAddress((void**)&pb,   g_b);

    cudaFuncSetAttribute(gemm_bf16x3,
                         cudaFuncAttributeMaxDynamicSharedMemorySize, 2 * ST_SZ);

    // --- one-time fp32 -> bf16 hi/lo splits into the MERGED X buffer
    {
        int n4 = SU * DIM_X / 4;
        cvt_hilo<<<(n4 + 255) / 256, 256>>>((const float4*)X_u,
                                            (uint2*)pXh, (uint2*)pXl, n4);
        int off4 = SU * DIM_X / 4;
        n4 = SL * DIM_X / 4;
        cvt_hilo<<<(n4 + 255) / 256, 256>>>((const float4*)X_l,
                                            (uint2*)pXh + off4, (uint2*)pXl + off4, n4);
        n4 = DIM_X * H1 / 4;
        cvt_hilo<<<(n4 + 255) / 256, 256>>>((const float4*)W1,
                                            (uint2*)pW1h, (uint2*)pW1l, n4);
        n4 = H1 * H2 / 4;
        cvt_hilo<<<(n4 + 255) / 256, 256>>>((const float4*)W2,
                                            (uint2*)pW2h, (uint2*)pW2l, n4);
    }

    // --- layer 1 (merged batch M = 24576): H = relu(X @ W1 + b1), bf16 hi/lo out
    gemm_bf16x3<<<dim3(H1 / BN, MT / BM), 256, 2 * ST_SZ>>>(
        pXh, pXl, pW1h, pW1l, b1,
        nullptr, nullptr, SU, pHh, pHl, MT, H1, DIM_X);

    // --- layer 2 (merged): feat = relu(H @ W2 + b2); rows<SU -> out_feat_u,
    //     rows>=SU -> g_feat_l
    gemm_bf16x3<<<dim3(H2 / BN, MT / BM), 256, 2 * ST_SZ>>>(
        pHh, pHl, pW2h, pW2l, b2,
        out_feat_u, pfl, SU, nullptr, nullptr, MT, H2, H1);

    // --- y_hat
    yhat_kernel<<<SL / 8, 256>>>(pfl, W3, b3, out_yhat);

    // --- pair sampling + combine
    sample_pairs_kernel<<<SU / 256, 256>>>(y_l, pa, pb);
    combine_kernel<<<SU, 128>>>(pfl, y_l, y_u, pa, pb, out_feat_comb);
}